// round 3
// baseline (speedup 1.0000x reference)
#include <cuda_runtime.h>
#include <cuda_bf16.h>

// KL(p||q) for diagonal Gaussians, mean over batch. Single fused kernel.
// Main loop: exact-trip-count grid-stride float4 streaming loads (__ldcs),
// #pragma unroll 4 so ptxas front-batches 16 independent LDG.128.
// Tail: last block (atomic ticket) reduces 1024 partials in fixed order
// (deterministic) and writes the scalar; ticket self-resets for graph replay.

#define NBLOCKS 1024
#define NTHREADS 256

__device__ float g_partials[NBLOCKS];
__device__ unsigned int g_ticket = 0;

__device__ __forceinline__ float kl_term(float pm, float pl, float qm, float ql)
{
    float lr = ql - pl;
    float dm = pm - qm;
    return lr + __expf(-lr) + dm * dm * __expf(-ql) - 1.0f;
}

__device__ __forceinline__ float kl_vec4(float4 a, float4 b, float4 c, float4 d)
{
    return kl_term(a.x, b.x, c.x, d.x)
         + kl_term(a.y, b.y, c.y, d.y)
         + kl_term(a.z, b.z, c.z, d.z)
         + kl_term(a.w, b.w, c.w, d.w);
}

__global__ __launch_bounds__(NTHREADS) void kl_fused_kernel(
    const float* __restrict__ p_mu,
    const float* __restrict__ p_lv,
    const float* __restrict__ q_mu,
    const float* __restrict__ q_lv,
    float* __restrict__ out,
    int n4, float scale)
{
    const float4* pm4 = reinterpret_cast<const float4*>(p_mu);
    const float4* pl4 = reinterpret_cast<const float4*>(p_lv);
    const float4* qm4 = reinterpret_cast<const float4*>(q_mu);
    const float4* ql4 = reinterpret_cast<const float4*>(q_lv);

    const int tid    = blockIdx.x * blockDim.x + threadIdx.x;
    const int stride = gridDim.x * blockDim.x;

    float acc = 0.0f;

    // Exact trip count: compiler-visible structure, unroll-4 => 16 LDG.128
    // front-batched per pass. Streaming (.cs) since data is read once.
    const int iters = n4 / stride;          // 8 for B=16384, D=512
    #pragma unroll 4
    for (int k = 0; k < iters; ++k) {
        int i = tid + k * stride;
        float4 a = __ldcs(&pm4[i]);
        float4 b = __ldcs(&pl4[i]);
        float4 c = __ldcs(&qm4[i]);
        float4 d = __ldcs(&ql4[i]);
        acc += kl_vec4(a, b, c, d);
    }
    // Remainder (empty when stride divides n4, kept for generality).
    for (int i = tid + iters * stride; i < n4; i += stride) {
        acc += kl_vec4(__ldcs(&pm4[i]), __ldcs(&pl4[i]),
                       __ldcs(&qm4[i]), __ldcs(&ql4[i]));
    }

    // Block reduce
    #pragma unroll
    for (int off = 16; off > 0; off >>= 1)
        acc += __shfl_down_sync(0xFFFFFFFFu, acc, off);

    __shared__ float smem[NTHREADS / 32];
    __shared__ bool s_is_last;
    const int lane = threadIdx.x & 31;
    const int warp = threadIdx.x >> 5;
    if (lane == 0) smem[warp] = acc;
    __syncthreads();

    if (warp == 0) {
        acc = (lane < NTHREADS / 32) ? smem[lane] : 0.0f;
        #pragma unroll
        for (int off = 4; off > 0; off >>= 1)
            acc += __shfl_down_sync(0xFFFFFFFFu, acc, off);
        if (lane == 0) {
            g_partials[blockIdx.x] = acc;
            __threadfence();
            unsigned int t = atomicAdd(&g_ticket, 1u);
            s_is_last = (t == (unsigned int)(gridDim.x - 1));
        }
    }
    __syncthreads();

    if (!s_is_last) return;

    // Last block: fixed-order reduce of all partials (deterministic).
    const volatile float* vp = (const volatile float*)g_partials;
    float tacc = 0.0f;
    for (int j = threadIdx.x; j < NBLOCKS; j += NTHREADS)
        tacc += vp[j];

    #pragma unroll
    for (int off = 16; off > 0; off >>= 1)
        tacc += __shfl_down_sync(0xFFFFFFFFu, tacc, off);

    if (lane == 0) smem[warp] = tacc;
    __syncthreads();

    if (warp == 0) {
        tacc = (lane < NTHREADS / 32) ? smem[lane] : 0.0f;
        #pragma unroll
        for (int off = 4; off > 0; off >>= 1)
            tacc += __shfl_down_sync(0xFFFFFFFFu, tacc, off);
        if (lane == 0) {
            out[0] = tacc * scale;
            g_ticket = 0;           // reset for next graph replay
            __threadfence();
        }
    }
}

extern "C" void kernel_launch(void* const* d_in, const int* in_sizes, int n_in,
                              void* d_out, int out_size)
{
    const float* p_mu = (const float*)d_in[0];
    const float* p_lv = (const float*)d_in[1];
    const float* q_mu = (const float*)d_in[2];
    const float* q_lv = (const float*)d_in[3];
    float* out = (float*)d_out;

    int n  = in_sizes[0];     // B*D
    int n4 = n >> 2;
    int B  = n / 512;         // D = 512
    float scale = 0.5f / (float)B;

    kl_fused_kernel<<<NBLOCKS, NTHREADS>>>(p_mu, p_lv, q_mu, q_lv, out, n4, scale);
}

// round 4
// speedup vs baseline: 1.2161x; 1.2161x over previous
#include <cuda_runtime.h>
#include <cuda_bf16.h>

// KL(p||q) for diagonal Gaussians, mean over batch. Fused single kernel:
// main loop is the EXACT round-1 grid-stride body (best measured codegen,
// ~6 TB/s); tail is the last-block (atomic ticket) fixed-order reduction
// of 1024 partials. Deterministic; ticket self-resets for graph replay.

#define NBLOCKS 1024
#define NTHREADS 256

__device__ float g_partials[NBLOCKS];
__device__ unsigned int g_ticket = 0;

__global__ __launch_bounds__(NTHREADS) void kl_fused_kernel(
    const float* __restrict__ p_mu,
    const float* __restrict__ p_lv,
    const float* __restrict__ q_mu,
    const float* __restrict__ q_lv,
    float* __restrict__ out,
    int n4, float scale)
{
    const float4* pm4 = reinterpret_cast<const float4*>(p_mu);
    const float4* pl4 = reinterpret_cast<const float4*>(p_lv);
    const float4* qm4 = reinterpret_cast<const float4*>(q_mu);
    const float4* ql4 = reinterpret_cast<const float4*>(q_lv);

    float acc = 0.0f;
    int stride = gridDim.x * blockDim.x;
    for (int i = blockIdx.x * blockDim.x + threadIdx.x; i < n4; i += stride) {
        float4 a = pm4[i];
        float4 b = pl4[i];
        float4 c = qm4[i];
        float4 d = ql4[i];

        {
            float lr = d.x - b.x;
            float dm = a.x - c.x;
            acc += lr + __expf(-lr) + dm * dm * __expf(-d.x) - 1.0f;
        }
        {
            float lr = d.y - b.y;
            float dm = a.y - c.y;
            acc += lr + __expf(-lr) + dm * dm * __expf(-d.y) - 1.0f;
        }
        {
            float lr = d.z - b.z;
            float dm = a.z - c.z;
            acc += lr + __expf(-lr) + dm * dm * __expf(-d.z) - 1.0f;
        }
        {
            float lr = d.w - b.w;
            float dm = a.w - c.w;
            acc += lr + __expf(-lr) + dm * dm * __expf(-d.w) - 1.0f;
        }
    }

    // Block reduce
    #pragma unroll
    for (int off = 16; off > 0; off >>= 1)
        acc += __shfl_down_sync(0xFFFFFFFFu, acc, off);

    __shared__ float smem[NTHREADS / 32];
    __shared__ bool s_is_last;
    const int lane = threadIdx.x & 31;
    const int warp = threadIdx.x >> 5;
    if (lane == 0) smem[warp] = acc;
    __syncthreads();

    if (warp == 0) {
        acc = (lane < NTHREADS / 32) ? smem[lane] : 0.0f;
        #pragma unroll
        for (int off = 4; off > 0; off >>= 1)
            acc += __shfl_down_sync(0xFFFFFFFFu, acc, off);
        if (lane == 0) {
            g_partials[blockIdx.x] = acc;
            __threadfence();
            unsigned int t = atomicAdd(&g_ticket, 1u);
            s_is_last = (t == (unsigned int)(gridDim.x - 1));
        }
    }
    __syncthreads();

    if (!s_is_last) return;

    // Last block: fixed-order reduce of all partials (deterministic).
    const volatile float* vp = (const volatile float*)g_partials;
    float tacc = 0.0f;
    for (int j = threadIdx.x; j < NBLOCKS; j += NTHREADS)
        tacc += vp[j];

    #pragma unroll
    for (int off = 16; off > 0; off >>= 1)
        tacc += __shfl_down_sync(0xFFFFFFFFu, tacc, off);

    if (lane == 0) smem[warp] = tacc;
    __syncthreads();

    if (warp == 0) {
        tacc = (lane < NTHREADS / 32) ? smem[lane] : 0.0f;
        #pragma unroll
        for (int off = 4; off > 0; off >>= 1)
            tacc += __shfl_down_sync(0xFFFFFFFFu, tacc, off);
        if (lane == 0) {
            out[0] = tacc * scale;
            g_ticket = 0;           // reset for next graph replay
            __threadfence();
        }
    }
}

extern "C" void kernel_launch(void* const* d_in, const int* in_sizes, int n_in,
                              void* d_out, int out_size)
{
    const float* p_mu = (const float*)d_in[0];
    const float* p_lv = (const float*)d_in[1];
    const float* q_mu = (const float*)d_in[2];
    const float* q_lv = (const float*)d_in[3];
    float* out = (float*)d_out;

    int n  = in_sizes[0];     // B*D
    int n4 = n >> 2;
    int B  = n / 512;         // D = 512
    float scale = 0.5f / (float)B;

    kl_fused_kernel<<<NBLOCKS, NTHREADS>>>(p_mu, p_lv, q_mu, q_lv, out, n4, scale);
}

// round 5
// speedup vs baseline: 1.2175x; 1.0012x over previous
#include <cuda_runtime.h>
#include <cuda_bf16.h>

// KL(p||q) for diagonal Gaussians, mean over batch. Fused single kernel.
// Round-1 loop body (best measured codegen) + last-block fixed-order tail.
// Change vs R4: 512-thread blocks (occ/SM halved -> oe*MLP_p1 ~ Q_th,
// kills cross-CTA L1tex-queue contention spread per the B300 model).

#define NBLOCKS 1024
#define NTHREADS 512

__device__ float g_partials[NBLOCKS];
__device__ unsigned int g_ticket = 0;

__global__ __launch_bounds__(NTHREADS) void kl_fused_kernel(
    const float* __restrict__ p_mu,
    const float* __restrict__ p_lv,
    const float* __restrict__ q_mu,
    const float* __restrict__ q_lv,
    float* __restrict__ out,
    int n4, float scale)
{
    const float4* pm4 = reinterpret_cast<const float4*>(p_mu);
    const float4* pl4 = reinterpret_cast<const float4*>(p_lv);
    const float4* qm4 = reinterpret_cast<const float4*>(q_mu);
    const float4* ql4 = reinterpret_cast<const float4*>(q_lv);

    float acc = 0.0f;
    int stride = gridDim.x * blockDim.x;
    for (int i = blockIdx.x * blockDim.x + threadIdx.x; i < n4; i += stride) {
        float4 a = pm4[i];
        float4 b = pl4[i];
        float4 c = qm4[i];
        float4 d = ql4[i];

        {
            float lr = d.x - b.x;
            float dm = a.x - c.x;
            acc += lr + __expf(-lr) + dm * dm * __expf(-d.x) - 1.0f;
        }
        {
            float lr = d.y - b.y;
            float dm = a.y - c.y;
            acc += lr + __expf(-lr) + dm * dm * __expf(-d.y) - 1.0f;
        }
        {
            float lr = d.z - b.z;
            float dm = a.z - c.z;
            acc += lr + __expf(-lr) + dm * dm * __expf(-d.z) - 1.0f;
        }
        {
            float lr = d.w - b.w;
            float dm = a.w - c.w;
            acc += lr + __expf(-lr) + dm * dm * __expf(-d.w) - 1.0f;
        }
    }

    // Block reduce
    #pragma unroll
    for (int off = 16; off > 0; off >>= 1)
        acc += __shfl_down_sync(0xFFFFFFFFu, acc, off);

    __shared__ float smem[NTHREADS / 32];
    __shared__ bool s_is_last;
    const int lane = threadIdx.x & 31;
    const int warp = threadIdx.x >> 5;
    if (lane == 0) smem[warp] = acc;
    __syncthreads();

    if (warp == 0) {
        acc = (lane < NTHREADS / 32) ? smem[lane] : 0.0f;
        #pragma unroll
        for (int off = 8; off > 0; off >>= 1)
            acc += __shfl_down_sync(0xFFFFFFFFu, acc, off);
        if (lane == 0) {
            g_partials[blockIdx.x] = acc;
            __threadfence();
            unsigned int t = atomicAdd(&g_ticket, 1u);
            s_is_last = (t == (unsigned int)(gridDim.x - 1));
        }
    }
    __syncthreads();

    if (!s_is_last) return;

    // Last block: fixed-order reduce of all partials (deterministic).
    const volatile float* vp = (const volatile float*)g_partials;
    float tacc = 0.0f;
    for (int j = threadIdx.x; j < NBLOCKS; j += NTHREADS)
        tacc += vp[j];

    #pragma unroll
    for (int off = 16; off > 0; off >>= 1)
        tacc += __shfl_down_sync(0xFFFFFFFFu, tacc, off);

    if (lane == 0) smem[warp] = tacc;
    __syncthreads();

    if (warp == 0) {
        tacc = (lane < NTHREADS / 32) ? smem[lane] : 0.0f;
        #pragma unroll
        for (int off = 8; off > 0; off >>= 1)
            tacc += __shfl_down_sync(0xFFFFFFFFu, tacc, off);
        if (lane == 0) {
            out[0] = tacc * scale;
            g_ticket = 0;           // reset for next graph replay
            __threadfence();
        }
    }
}

extern "C" void kernel_launch(void* const* d_in, const int* in_sizes, int n_in,
                              void* d_out, int out_size)
{
    const float* p_mu = (const float*)d_in[0];
    const float* p_lv = (const float*)d_in[1];
    const float* q_mu = (const float*)d_in[2];
    const float* q_lv = (const float*)d_in[3];
    float* out = (float*)d_out;

    int n  = in_sizes[0];     // B*D
    int n4 = n >> 2;
    int B  = n / 512;         // D = 512
    float scale = 0.5f / (float)B;

    kl_fused_kernel<<<NBLOCKS, NTHREADS>>>(p_mu, p_lv, q_mu, q_lv, out, n4, scale);
}